// round 12
// baseline (speedup 1.0000x reference)
#include <cuda_runtime.h>
#include <cuda_bf16.h>
#include <math.h>

#define NN 20000
#define EE 640000
#define TT 4096

typedef unsigned long long ULL;

// ---------------- packed f32x2 helpers -------------------------------------
__device__ __forceinline__ ULL pk2(float lo, float hi) {
    ULL r; asm("mov.b64 %0,{%1,%2};" : "=l"(r) : "f"(lo), "f"(hi)); return r;
}
__device__ __forceinline__ ULL dup2(float v) { return pk2(v, v); }
__device__ __forceinline__ void upk2(ULL v, float& lo, float& hi) {
    asm("mov.b64 {%0,%1},%2;" : "=f"(lo), "=f"(hi) : "l"(v));
}
__device__ __forceinline__ void fma2(ULL& d, ULL a, ULL b) {
    asm("fma.rn.f32x2 %0,%1,%2,%0;" : "+l"(d) : "l"(a), "l"(b));
}
__device__ __forceinline__ ULL mul2(ULL a, ULL b) {
    ULL d; asm("mul.rn.f32x2 %0,%1,%2;" : "=l"(d) : "l"(a), "l"(b)); return d;
}

// ---------------- cp.async helpers ------------------------------------------
__device__ __forceinline__ void cpa16(void* smem_dst, const void* gsrc) {
    unsigned s = (unsigned)__cvta_generic_to_shared(smem_dst);
    asm volatile("cp.async.cg.shared.global [%0],[%1],16;" :: "r"(s), "l"(gsrc));
}
#define CP_COMMIT asm volatile("cp.async.commit_group;")

// ---------------- vector RED ------------------------------------------------
__device__ __forceinline__ void red_v4(float* p, float a, float b, float c, float d) {
    asm volatile("red.global.add.v4.f32 [%0],{%1,%2,%3,%4};"
                 :: "l"(p), "f"(a), "f"(b), "f"(c), "f"(d) : "memory");
}

__device__ __forceinline__ float fsilu(float x) {
    return x * __fdividef(1.0f, 1.0f + __expf(-x));
}
__device__ __forceinline__ float fsig(float x) {
    return __fdividef(1.0f, 1.0f + __expf(-x));
}

// ---------------- scratch ----------------------------------------------------
__device__ float4 g_geo[EE];        // {x, Y0, Y1, Y2} (unsorted)
__device__ int2   g_se[EE];         // {snd, rcv} (unsorted)
__device__ float4 g_geo2[EE];       // sorted by rcv
__device__ int2   g_se2[EE];        // sorted by rcv
__device__ int    g_hist[NN];
__device__ int    g_cur[NN];
__device__ float  g_sv[NN * 128];   // [n][f]{s,v0,v1,v2} packed float4
__device__ float  g_agg[NN * 128];  // same packing
__device__ float  g_pre[NN * 160];  // [n][p][32]
__device__ float  g_wdup[786432];   // duplicated node weights, 2 layers
__device__ float  g_tab[2 * TT * 160];             // radial values * INV
__device__ __nv_bfloat16 g_tabS[2 * TT * 160];     // slopes (bf16)

// ---------------- radial table build (runs once, 2*4096 points) -------------
__global__ void tab_kernel(const float* __restrict__ rW1,
                           const float* __restrict__ rb1,
                           const float* __restrict__ rW2) {
    int l = blockIdx.x >> 12;
    int i = blockIdx.x & (TT - 1);
    int tid = threadIdx.x;       // 160 threads
    __shared__ float H[64];
    float x = (float)i * (1.0f / (float)(TT - 1));
    float xe = fmaxf(x, 1e-7f);
    if (tid < 64) {
        float r = 5.0f * xe;
        float x3 = xe * xe * xe;
        float x6 = x3 * x3;
        float x7 = x6 * xe;
        float x8 = x7 * xe;
        float fc = (xe < 1.0f) ? (1.0f - 28.0f * x6 + 48.0f * x7 - 21.0f * x8) : 0.0f;
        float c = 0.6324555320336759f * fc / r;
        float acc = rb1[l * 64 + tid];
#pragma unroll
        for (int n = 1; n <= 8; n++) {
            float ef = c * sinf((float)n * 3.14159265358979323846f * xe);
            acc += ef * rW1[l * 512 + (n - 1) * 64 + tid];
        }
        H[tid] = acc / (1.0f + expf(-acc));
    }
    __syncthreads();
    float out = 0.0f;
#pragma unroll 8
    for (int k = 0; k < 64; k++)
        out += H[k] * rW2[l * 10240 + k * 160 + tid];
    g_tab[((long)l * TT + i) * 160 + tid] = out * 0.17677669529663689f;
}

// ---------------- slope table (bf16) -----------------------------------------
__global__ void slope_kernel() {
    int idx = blockIdx.x * 256 + threadIdx.x;
    if (idx >= 2 * TT * 160) return;
    int i = (idx / 160) & (TT - 1);
    float v = g_tab[idx];
    float vn = (i < TT - 1) ? g_tab[idx + 160] : v;
    g_tabS[idx] = __float2bfloat16(vn - v);
}

// ---------------- weight duplication (runs once) ----------------------------
__global__ void dupw_kernel(const float* __restrict__ Ws,
                            const float* __restrict__ Wv) {
    int idx = blockIdx.x * 256 + threadIdx.x;   // < 786432
    int l = idx / 393216;
    int rem = idx - l * 393216;
    int f = rem / 12288;
    int a = (rem / 192) % 64;
    int c = rem % 192;
    float v;
    if (c < 128)
        v = Ws[(long)l * 131072 + f * 4096 + a * 64 + (c >> 1)];
    else
        v = Wv[(long)l * 65536 + f * 2048 + a * 32 + ((c - 128) >> 1)];
    g_wdup[idx] = v;
}

// ---------------- edge geometry + rcv histogram ------------------------------
__global__ void geom_kernel(const float* __restrict__ coords,
                            const int* __restrict__ eidx) {
    int e = blockIdx.x * blockDim.x + threadIdx.x;
    if (e >= EE) return;
    int snd = eidx[e];
    int rcv = eidx[EE + e];
    float dx = coords[snd * 3 + 0] - coords[rcv * 3 + 0];
    float dy = coords[snd * 3 + 1] - coords[rcv * 3 + 1];
    float dz = coords[snd * 3 + 2] - coords[rcv * 3 + 2];
    float r = sqrtf(dx * dx + dy * dy + dz * dz + 1e-12f);
    float invr = 1.0f / r;
    float sc = 1.7320508075688772f * invr;
    g_geo[e] = make_float4(r * 0.2f, sc * dx, sc * dy, sc * dz);
    g_se[e] = make_int2(snd, rcv);
    atomicAdd(&g_hist[rcv], 1);
}

// ---------------- exclusive scan of histogram (single block) ----------------
__global__ void scan_kernel() {
    __shared__ int tmp[1024];
    __shared__ int carry;
    if (threadIdx.x == 0) carry = 0;
    __syncthreads();
    for (int base = 0; base < NN; base += 1024) {
        int i = base + threadIdx.x;
        int v = (i < NN) ? g_hist[i] : 0;
        tmp[threadIdx.x] = v;
        __syncthreads();
        for (int off = 1; off < 1024; off <<= 1) {
            int t = (threadIdx.x >= off) ? tmp[threadIdx.x - off] : 0;
            __syncthreads();
            tmp[threadIdx.x] += t;
            __syncthreads();
        }
        if (i < NN) g_cur[i] = tmp[threadIdx.x] - v + carry;
        int total = tmp[1023];
        __syncthreads();
        if (threadIdx.x == 0) carry += total;
        __syncthreads();
    }
}

// ---------------- scatter edges into rcv-sorted order ------------------------
__global__ void scatter_kernel() {
    int e = blockIdx.x * 256 + threadIdx.x;
    if (e >= EE) return;
    int2 se = g_se[e];
    int pos = atomicAdd(&g_cur[se.y], 1);
    g_se2[pos] = se;
    g_geo2[pos] = g_geo[e];
}

// ---------------- node embedding -------------------------------------------
__global__ void emb_kernel(const float* __restrict__ attrs,
                           const float* __restrict__ W) {
    int gid = blockIdx.x * 256 + threadIdx.x;
    int n = gid >> 5;
    int f = gid & 31;
    float acc = 0.0f;
#pragma unroll 8
    for (int a = 0; a < 64; a++) acc += attrs[n * 64 + a] * W[a * 32 + f];
    ((float4*)g_sv)[gid] = make_float4(acc, 0.0f, 0.0f, 0.0f);
}

// ---------------- edge kernel: sorted edges, batch-4 MLP + run merge --------
__global__ __launch_bounds__(256) void edge_kernel(
        const float* __restrict__ tabV,
        const __nv_bfloat16* __restrict__ tabS) {
    int gw = (blockIdx.x * 256 + threadIdx.x) >> 5;
    int tx = threadIdx.x & 31;
    int nw = (gridDim.x * 256) >> 5;
    int per = (EE + nw - 1) / nw;
    int e0 = gw * per;
    int e1 = min(e0 + per, EE);

    const float4* sv4 = (const float4*)g_sv;

    int prev = -1;
    float am = 0.f, a0 = 0.f, a1 = 0.f, a2 = 0.f;

    for (int eb = e0; eb < e1; eb += 4) {
        int nb = min(4, e1 - eb);
        int2   sr[4];
        float4 gy[4];
        float4 sv[4];
        float  w[4][5];

        // phase 1: issue all independent loads (restores MLP)
#pragma unroll
        for (int j = 0; j < 4; j++) {
            if (j < nb) {
                sr[j] = __ldg(&g_se2[eb + j]);
                gy[j] = __ldg(&g_geo2[eb + j]);
            }
        }
#pragma unroll
        for (int j = 0; j < 4; j++) {
            if (j < nb) {
                sv[j] = __ldg(&sv4[(long)sr[j].x * 32 + tx]);
                float u = fminf(gy[j].x, 1.0f) * (float)(TT - 1);
                int ix = min((int)u, TT - 2);
                float fr = u - (float)ix;
                const float* vp = tabV + (long)ix * 160 + tx;
                const __nv_bfloat16* sp = tabS + (long)ix * 160 + tx;
#pragma unroll
                for (int p = 0; p < 5; p++) {
                    float sl = __bfloat162float(__ldg(sp + p * 32));
                    w[j][p] = fmaf(fr, sl, __ldg(vp + p * 32));
                }
            }
        }

        // phase 2: compute messages + merge by rcv run (warp-uniform branch)
#pragma unroll
        for (int j = 0; j < 4; j++) {
            if (j < nb) {
                float y0 = gy[j].y, y1 = gy[j].z, y2 = gy[j].w;
                float sj = sv[j].x, vj0 = sv[j].y, vj1 = sv[j].z, vj2 = sv[j].w;
                float dot = vj0 * y0 + vj1 * y1 + vj2 * y2;
                float cx = vj1 * y2 - vj2 * y1;
                float cy = vj2 * y0 - vj0 * y2;
                float cz = vj0 * y1 - vj1 * y0;
                float ms  = w[j][0] * sj + w[j][3] * dot;
                float mv0 = w[j][1] * sj * y0 + w[j][2] * vj0 + w[j][4] * cx;
                float mv1 = w[j][1] * sj * y1 + w[j][2] * vj1 + w[j][4] * cy;
                float mv2 = w[j][1] * sj * y2 + w[j][2] * vj2 + w[j][4] * cz;
                if (sr[j].y != prev) {
                    if (prev >= 0)
                        red_v4(&g_agg[((long)prev * 32 + tx) * 4], am, a0, a1, a2);
                    prev = sr[j].y; am = ms; a0 = mv0; a1 = mv1; a2 = mv2;
                } else {
                    am += ms; a0 += mv0; a1 += mv1; a2 += mv2;
                }
            }
        }
    }
    if (prev >= 0)
        red_v4(&g_agg[((long)prev * 32 + tx) * 4], am, a0, a1, a2);
}

// ---------------- node update (64-node tiles, f-split 4, a-first factoring) -
#define NODE_SMEM_BYTES (20864 * 4)
#define NTILES 313   // ceil(20000/64)

__device__ __forceinline__ void node_issue_stage(float* ring,
        const float* __restrict__ Wd, int s, int tid) {
    float* dst = ring + (s & 3) * 3072;
    const float4* src = (const float4*)(Wd + (s >> 2) * 12288 + (s & 3) * 3072);
    float4* d = (float4*)dst;
#pragma unroll
    for (int i = 0; i < 3; i++) cpa16(d + tid + i * 256, src + tid + i * 256);
}

__global__ __launch_bounds__(256, 2) void node_kernel(
    const float* __restrict__ attrs,
    const float* __restrict__ Ls, const float* __restrict__ Lv,
    const float* __restrict__ Wdup) {
    extern __shared__ float sm[];
    float* sW   = sm;            // 4 x 3072 ring
    float* sAtT = sm + 12288;    // [a][n] stride 68
    float* sST  = sAtT + 4352;   // [f_local][n] stride 66 (8 rows)
    float* sVT  = sST + 528;     // [c*8+f_local][n] stride 66 (24 rows)
    float* sAgS = sVT + 1584;
    float* sAgV = sAgS + 528;

    int tid = threadIdx.x, tx = tid & 31, ty = tid >> 5;
    int tile = blockIdx.x >> 2;
    int F0 = (blockIdx.x & 3) * 8;
    int base = tile * 64;
    int nA = ty * 8;
    const float* Wd = Wdup + (long)F0 * 12288;

    node_issue_stage(sW, Wd, 0, tid); CP_COMMIT;
    node_issue_stage(sW, Wd, 1, tid); CP_COMMIT;

    const float4* sv4 = (const float4*)g_sv;
    const float4* ag4 = (const float4*)g_agg;
    for (int i = tid; i < 512; i += 256) {
        int fl = i & 7, n = i >> 3;
        int gn = base + n;
        float4 a = (gn < NN) ? sv4[(long)gn * 32 + F0 + fl]
                             : make_float4(0.f, 0.f, 0.f, 0.f);
        float4 b = (gn < NN) ? ag4[(long)gn * 32 + F0 + fl]
                             : make_float4(0.f, 0.f, 0.f, 0.f);
        sST[fl * 66 + n] = a.x;
        sVT[fl * 66 + n] = a.y;
        sVT[(8 + fl) * 66 + n] = a.z;
        sVT[(16 + fl) * 66 + n] = a.w;
        sAgS[fl * 66 + n] = b.x;
        sAgV[fl * 66 + n] = b.y;
        sAgV[(8 + fl) * 66 + n] = b.z;
        sAgV[(16 + fl) * 66 + n] = b.w;
    }
    for (int i = tid; i < 4096; i += 256) {
        int a = i & 63, n = i >> 6;
        int gn = base + n;
        sAtT[a * 68 + n] = (gn < NN) ? attrs[(long)gn * 64 + a] : 0.0f;
    }

    ULL acc0[4] = {0,0,0,0}, acc1[4] = {0,0,0,0}, acc2[4] = {0,0,0,0},
        acc3[4] = {0,0,0,0}, acc4[4] = {0,0,0,0};

    int qi = 0;
    for (int fl = 0; fl < 8; fl++) {
        int fg = F0 + fl;
        ULL Ls02 = dup2(__ldg(&Ls[fg * 64 + tx]));
        ULL Ls12 = dup2(__ldg(&Ls[fg * 64 + 32 + tx]));
        ULL Lv02 = dup2(__ldg(&Lv[fg * 32 + tx]));

        if (fl == 0) __syncthreads();   // node arrays ready

        // lin parts
#pragma unroll
        for (int P = 0; P < 4; P++) {
            int nn = nA + 2 * P;
            ULL ag = *(const ULL*)&sAgS[fl * 66 + nn];
            fma2(acc0[P], ag, Ls02);
            fma2(acc1[P], ag, Ls12);
            fma2(acc2[P], *(const ULL*)&sAgV[fl * 66 + nn], Lv02);
            fma2(acc3[P], *(const ULL*)&sAgV[(8 + fl) * 66 + nn], Lv02);
            fma2(acc4[P], *(const ULL*)&sAgV[(16 + fl) * 66 + nn], Lv02);
        }

        // a-first accumulators
        ULL E0[4] = {0,0,0,0}, E1[4] = {0,0,0,0}, Dd[4] = {0,0,0,0};

#pragma unroll 1
        for (int q = 0; q < 4; q++, qi++) {
            if (qi + 2 < 32) node_issue_stage(sW, Wd, qi + 2, tid);
            CP_COMMIT;
            asm volatile("cp.async.wait_group 2;");
            __syncthreads();

            const float* sWq = sW + (qi & 3) * 3072;
#pragma unroll 4
            for (int aa = 0; aa < 16; aa++) {
                int ag_ = q * 16 + aa;
                ULL W02  = *(const ULL*)&sWq[aa * 192 + tx * 2];
                ULL W12  = *(const ULL*)&sWq[aa * 192 + 64 + tx * 2];
                ULL Wv02 = *(const ULL*)&sWq[aa * 192 + 128 + tx * 2];
                ulonglong2 atA = *(const ulonglong2*)&sAtT[ag_ * 68 + nA];
                ulonglong2 atB = *(const ulonglong2*)&sAtT[ag_ * 68 + nA + 4];
                fma2(E0[0], atA.x, W02); fma2(E1[0], atA.x, W12); fma2(Dd[0], atA.x, Wv02);
                fma2(E0[1], atA.y, W02); fma2(E1[1], atA.y, W12); fma2(Dd[1], atA.y, Wv02);
                fma2(E0[2], atB.x, W02); fma2(E1[2], atB.x, W12); fma2(Dd[2], atB.x, Wv02);
                fma2(E0[3], atB.y, W02); fma2(E1[3], atB.y, W12); fma2(Dd[3], atB.y, Wv02);
            }
        }

        // per-f epilogue
#pragma unroll
        for (int P = 0; P < 4; P++) {
            int nn = nA + 2 * P;
            ULL sf2 = *(const ULL*)&sST[fl * 66 + nn];
            fma2(acc0[P], sf2, E0[P]);
            fma2(acc1[P], sf2, E1[P]);
            fma2(acc2[P], *(const ULL*)&sVT[fl * 66 + nn], Dd[P]);
            fma2(acc3[P], *(const ULL*)&sVT[(8 + fl) * 66 + nn], Dd[P]);
            fma2(acc4[P], *(const ULL*)&sVT[(16 + fl) * 66 + nn], Dd[P]);
        }
    }

    // epilogue: RED partial sums into g_pre
#pragma unroll
    for (int P = 0; P < 4; P++) {
        float ft[2], gt[2], a2[2], a3[2], a4[2];
        upk2(acc0[P], ft[0], ft[1]);
        upk2(acc1[P], gt[0], gt[1]);
        upk2(acc2[P], a2[0], a2[1]);
        upk2(acc3[P], a3[0], a3[1]);
        upk2(acc4[P], a4[0], a4[1]);
#pragma unroll
        for (int h = 0; h < 2; h++) {
            int gn = base + nA + 2 * P + h;
            if (gn < NN) {
                float* p = g_pre + (long)gn * 160 + tx;
                atomicAdd(p, ft[h]);
                atomicAdd(p + 32, gt[h]);
                atomicAdd(p + 64, a2[h]);
                atomicAdd(p + 96, a3[h]);
                atomicAdd(p + 128, a4[h]);
            }
        }
    }
}

// ---------------- node epilogue ---------------------------------------------
__global__ void epi_kernel() {
    int idx = blockIdx.x * 256 + threadIdx.x;
    if (idx >= NN * 32) return;
    int n = idx >> 5, tx = idx & 31;
    const float* p = g_pre + (long)n * 160 + tx;
    float ft = p[0], gt = p[32], a2 = p[64], a3 = p[96], a4 = p[128];
    float4 o = ((float4*)g_sv)[idx];
    float sg = fsig(gt);
    float s_new = fsilu(ft) + o.x;
    ((float4*)g_sv)[idx] =
        make_float4(s_new, a2 * sg + o.y, a3 * sg + o.z, a4 * sg + o.w);
}

// ---------------- output assembly -------------------------------------------
__global__ void out_kernel(float* __restrict__ out) {
    int idx = blockIdx.x * 256 + threadIdx.x;
    if (idx >= NN * 128) return;
    int n = idx >> 7, j = idx & 127;
    float val;
    if (j < 32) {
        val = g_sv[((long)n * 32 + j) * 4];
    } else {
        int t = j - 32;
        int f = t / 3;
        int c = t - 3 * f;
        val = g_sv[((long)n * 32 + f) * 4 + 1 + c];
    }
    out[idx] = val;
}

// ---------------- launch -----------------------------------------------------
extern "C" void kernel_launch(void* const* d_in, const int* in_sizes, int n_in,
                              void* d_out, int out_size) {
    const float* attrs  = (const float*)d_in[0];
    const float* coords = (const float*)d_in[1];
    const int*   eidx   = (const int*)d_in[2];
    const float* embW   = (const float*)d_in[3];
    const float* rW1    = (const float*)d_in[4];
    const float* rb1    = (const float*)d_in[5];
    const float* rW2    = (const float*)d_in[6];
    const float* Ls     = (const float*)d_in[7];
    const float* Lv     = (const float*)d_in[8];
    const float* Ws     = (const float*)d_in[9];
    const float* Wv     = (const float*)d_in[10];
    float* out = (float*)d_out;

    cudaFuncSetAttribute(node_kernel,
                         cudaFuncAttributeMaxDynamicSharedMemorySize,
                         NODE_SMEM_BYTES);

    void *pagg = nullptr, *ppre = nullptr, *pwd = nullptr;
    void *ptab = nullptr, *ptabS = nullptr, *phist = nullptr;
    cudaGetSymbolAddress(&pagg, g_agg);
    cudaGetSymbolAddress(&ppre, g_pre);
    cudaGetSymbolAddress(&pwd, g_wdup);
    cudaGetSymbolAddress(&ptab, g_tab);
    cudaGetSymbolAddress(&ptabS, g_tabS);
    cudaGetSymbolAddress(&phist, g_hist);

    cudaMemsetAsync(phist, 0, NN * sizeof(int));
    tab_kernel<<<2 * TT, 160>>>(rW1, rb1, rW2);
    slope_kernel<<<(2 * TT * 160 + 255) / 256, 256>>>();
    dupw_kernel<<<3072, 256>>>(Ws, Wv);
    geom_kernel<<<(EE + 255) / 256, 256>>>(coords, eidx);
    scan_kernel<<<1, 1024>>>();
    scatter_kernel<<<(EE + 255) / 256, 256>>>();
    emb_kernel<<<NN * 32 / 256, 256>>>(attrs, embW);

    for (int l = 0; l < 2; l++) {
        cudaMemsetAsync(pagg, 0, NN * 128 * sizeof(float));
        cudaMemsetAsync(ppre, 0, NN * 160 * sizeof(float));
        edge_kernel<<<1184, 256>>>(
            (const float*)ptab + (long)l * TT * 160,
            (const __nv_bfloat16*)ptabS + (long)l * TT * 160);
        node_kernel<<<NTILES * 4, 256, NODE_SMEM_BYTES>>>(
            attrs, Ls + l * 2048, Lv + l * 1024,
            (const float*)pwd + (long)l * 393216);
        epi_kernel<<<(NN * 32 + 255) / 256, 256>>>();
    }
    out_kernel<<<(NN * 128 + 255) / 256, 256>>>(out);
}

// round 13
// speedup vs baseline: 1.1840x; 1.1840x over previous
#include <cuda_runtime.h>
#include <cuda_bf16.h>
#include <math.h>

#define NN 20000
#define EE 640000
#define TT 4096

typedef unsigned long long ULL;

// ---------------- packed f32x2 helpers -------------------------------------
__device__ __forceinline__ ULL pk2(float lo, float hi) {
    ULL r; asm("mov.b64 %0,{%1,%2};" : "=l"(r) : "f"(lo), "f"(hi)); return r;
}
__device__ __forceinline__ ULL dup2(float v) { return pk2(v, v); }
__device__ __forceinline__ void upk2(ULL v, float& lo, float& hi) {
    asm("mov.b64 {%0,%1},%2;" : "=f"(lo), "=f"(hi) : "l"(v));
}
__device__ __forceinline__ void fma2(ULL& d, ULL a, ULL b) {
    asm("fma.rn.f32x2 %0,%1,%2,%0;" : "+l"(d) : "l"(a), "l"(b));
}
__device__ __forceinline__ ULL mul2(ULL a, ULL b) {
    ULL d; asm("mul.rn.f32x2 %0,%1,%2;" : "=l"(d) : "l"(a), "l"(b)); return d;
}

// ---------------- cp.async helpers ------------------------------------------
__device__ __forceinline__ void cpa16(void* smem_dst, const void* gsrc) {
    unsigned s = (unsigned)__cvta_generic_to_shared(smem_dst);
    asm volatile("cp.async.cg.shared.global [%0],[%1],16;" :: "r"(s), "l"(gsrc));
}
#define CP_COMMIT asm volatile("cp.async.commit_group;")

// ---------------- vector RED ------------------------------------------------
__device__ __forceinline__ void red_v4(float* p, float a, float b, float c, float d) {
    asm volatile("red.global.add.v4.f32 [%0],{%1,%2,%3,%4};"
                 :: "l"(p), "f"(a), "f"(b), "f"(c), "f"(d) : "memory");
}

__device__ __forceinline__ float fsilu(float x) {
    return x * __fdividef(1.0f, 1.0f + __expf(-x));
}
__device__ __forceinline__ float fsig(float x) {
    return __fdividef(1.0f, 1.0f + __expf(-x));
}

// ---------------- scratch ----------------------------------------------------
__device__ float4 g_geo[EE];        // {x, Y0, Y1, Y2}
__device__ int2   g_se[EE];         // {snd, rcv}
__device__ float  g_sv[NN * 128];   // [n][f]{s,v0,v1,v2} packed float4
__device__ float  g_agg[NN * 128];  // same packing
__device__ float  g_pre4[4 * NN * 160];  // 4 f-split partial slabs (plain ST)
__device__ float  g_wdup[786432];   // duplicated node weights, 2 layers
__device__ float  g_tab[2 * TT * 160];             // radial values * INV
__device__ __nv_bfloat16 g_tabS[2 * TT * 160];     // slopes (bf16)

// ---------------- radial table build (runs once, 2*4096 points) -------------
__global__ void tab_kernel(const float* __restrict__ rW1,
                           const float* __restrict__ rb1,
                           const float* __restrict__ rW2) {
    int l = blockIdx.x >> 12;
    int i = blockIdx.x & (TT - 1);
    int tid = threadIdx.x;       // 160 threads
    __shared__ float H[64];
    float x = (float)i * (1.0f / (float)(TT - 1));
    float xe = fmaxf(x, 1e-7f);
    if (tid < 64) {
        float r = 5.0f * xe;
        float x3 = xe * xe * xe;
        float x6 = x3 * x3;
        float x7 = x6 * xe;
        float x8 = x7 * xe;
        float fc = (xe < 1.0f) ? (1.0f - 28.0f * x6 + 48.0f * x7 - 21.0f * x8) : 0.0f;
        float c = 0.6324555320336759f * fc / r;
        float acc = rb1[l * 64 + tid];
#pragma unroll
        for (int n = 1; n <= 8; n++) {
            float ef = c * sinf((float)n * 3.14159265358979323846f * xe);
            acc += ef * rW1[l * 512 + (n - 1) * 64 + tid];
        }
        H[tid] = acc / (1.0f + expf(-acc));
    }
    __syncthreads();
    float out = 0.0f;
#pragma unroll 8
    for (int k = 0; k < 64; k++)
        out += H[k] * rW2[l * 10240 + k * 160 + tid];
    g_tab[((long)l * TT + i) * 160 + tid] = out * 0.17677669529663689f;
}

// ---------------- slope table (bf16) -----------------------------------------
__global__ void slope_kernel() {
    int idx = blockIdx.x * 256 + threadIdx.x;
    if (idx >= 2 * TT * 160) return;
    int i = (idx / 160) & (TT - 1);
    float v = g_tab[idx];
    float vn = (i < TT - 1) ? g_tab[idx + 160] : v;
    g_tabS[idx] = __float2bfloat16(vn - v);
}

// ---------------- weight duplication (runs once) ----------------------------
__global__ void dupw_kernel(const float* __restrict__ Ws,
                            const float* __restrict__ Wv) {
    int idx = blockIdx.x * 256 + threadIdx.x;   // < 786432
    int l = idx / 393216;
    int rem = idx - l * 393216;
    int f = rem / 12288;
    int a = (rem / 192) % 64;
    int c = rem % 192;
    float v;
    if (c < 128)
        v = Ws[(long)l * 131072 + f * 4096 + a * 64 + (c >> 1)];
    else
        v = Wv[(long)l * 65536 + f * 2048 + a * 32 + ((c - 128) >> 1)];
    g_wdup[idx] = v;
}

// ---------------- edge geometry ---------------------------------------------
__global__ void geom_kernel(const float* __restrict__ coords,
                            const int* __restrict__ eidx) {
    int e = blockIdx.x * blockDim.x + threadIdx.x;
    if (e >= EE) return;
    int snd = eidx[e];
    int rcv = eidx[EE + e];
    float dx = coords[snd * 3 + 0] - coords[rcv * 3 + 0];
    float dy = coords[snd * 3 + 1] - coords[rcv * 3 + 1];
    float dz = coords[snd * 3 + 2] - coords[rcv * 3 + 2];
    float r = sqrtf(dx * dx + dy * dy + dz * dz + 1e-12f);
    float invr = 1.0f / r;
    float sc = 1.7320508075688772f * invr;
    g_geo[e] = make_float4(r * 0.2f, sc * dx, sc * dy, sc * dz);
    g_se[e] = make_int2(snd, rcv);
}

// ---------------- node embedding -------------------------------------------
__global__ void emb_kernel(const float* __restrict__ attrs,
                           const float* __restrict__ W) {
    int gid = blockIdx.x * 256 + threadIdx.x;
    int n = gid >> 5;
    int f = gid & 31;
    float acc = 0.0f;
#pragma unroll 8
    for (int a = 0; a < 64; a++) acc += attrs[n * 64 + a] * W[a * 32 + f];
    ((float4*)g_sv)[gid] = make_float4(acc, 0.0f, 0.0f, 0.0f);
}

// ---------------- edge kernel: bf16-slope table lerp + message + scatter ----
// unsorted edges, per-edge independent red.v4 (max MLP) — proven R10 version
__global__ __launch_bounds__(256) void edge_kernel(
        const float* __restrict__ tabV,
        const __nv_bfloat16* __restrict__ tabS) {
    int gw = (blockIdx.x * 256 + threadIdx.x) >> 5;
    int tx = threadIdx.x & 31;
    int nw = (gridDim.x * 256) >> 5;
    int per = (EE + nw - 1) / nw;
    int e0 = gw * per;
    int e1 = min(e0 + per, EE);

    const float4* sv4 = (const float4*)g_sv;

    for (int e = e0; e < e1; e++) {
        int2 sr = __ldg(&g_se[e]);
        float4 gy = __ldg(&g_geo[e]);

        float u = fminf(gy.x, 1.0f) * (float)(TT - 1);
        int ix = min((int)u, TT - 2);
        float fr = u - (float)ix;

        const float* vp = tabV + (long)ix * 160 + tx;
        const __nv_bfloat16* sp = tabS + (long)ix * 160 + tx;
        float w[5];
#pragma unroll
        for (int p = 0; p < 5; p++) {
            float sl = __bfloat162float(__ldg(sp + p * 32));
            w[p] = fmaf(fr, sl, __ldg(vp + p * 32));
        }

        float4 sv = __ldg(&sv4[(long)sr.x * 32 + tx]);
        float y0 = gy.y, y1 = gy.z, y2 = gy.w;
        float sj = sv.x, vj0 = sv.y, vj1 = sv.z, vj2 = sv.w;
        float dot = vj0 * y0 + vj1 * y1 + vj2 * y2;
        float cx = vj1 * y2 - vj2 * y1;
        float cy = vj2 * y0 - vj0 * y2;
        float cz = vj0 * y1 - vj1 * y0;
        float ms  = w[0] * sj + w[3] * dot;             // INV folded in table
        float mv0 = w[1] * sj * y0 + w[2] * vj0 + w[4] * cx;
        float mv1 = w[1] * sj * y1 + w[2] * vj1 + w[4] * cy;
        float mv2 = w[1] * sj * y2 + w[2] * vj2 + w[4] * cz;
        red_v4(&g_agg[((long)sr.y * 32 + tx) * 4], ms, mv0, mv1, mv2);
    }
}

// ---------------- node update (64-node tiles, f-split 4, a-first factoring) -
#define NODE_SMEM_BYTES (20864 * 4)
#define NTILES 313   // ceil(20000/64)

__device__ __forceinline__ void node_issue_stage(float* ring,
        const float* __restrict__ Wd, int s, int tid) {
    float* dst = ring + (s & 3) * 3072;
    const float4* src = (const float4*)(Wd + (s >> 2) * 12288 + (s & 3) * 3072);
    float4* d = (float4*)dst;
#pragma unroll
    for (int i = 0; i < 3; i++) cpa16(d + tid + i * 256, src + tid + i * 256);
}

__global__ __launch_bounds__(256, 2) void node_kernel(
    const float* __restrict__ attrs,
    const float* __restrict__ Ls, const float* __restrict__ Lv,
    const float* __restrict__ Wdup) {
    extern __shared__ float sm[];
    float* sW   = sm;            // 4 x 3072 ring
    float* sAtT = sm + 12288;    // [a][n] stride 68
    float* sST  = sAtT + 4352;   // [f_local][n] stride 66 (8 rows)
    float* sVT  = sST + 528;     // [c*8+f_local][n] stride 66 (24 rows)
    float* sAgS = sVT + 1584;
    float* sAgV = sAgS + 528;

    int tid = threadIdx.x, tx = tid & 31, ty = tid >> 5;
    int tile = blockIdx.x >> 2;
    int fsp = blockIdx.x & 3;
    int F0 = fsp * 8;
    int base = tile * 64;
    int nA = ty * 8;
    const float* Wd = Wdup + (long)F0 * 12288;

    node_issue_stage(sW, Wd, 0, tid); CP_COMMIT;
    node_issue_stage(sW, Wd, 1, tid); CP_COMMIT;

    const float4* sv4 = (const float4*)g_sv;
    const float4* ag4 = (const float4*)g_agg;
    for (int i = tid; i < 512; i += 256) {
        int fl = i & 7, n = i >> 3;
        int gn = base + n;
        float4 a = (gn < NN) ? sv4[(long)gn * 32 + F0 + fl]
                             : make_float4(0.f, 0.f, 0.f, 0.f);
        float4 b = (gn < NN) ? ag4[(long)gn * 32 + F0 + fl]
                             : make_float4(0.f, 0.f, 0.f, 0.f);
        sST[fl * 66 + n] = a.x;
        sVT[fl * 66 + n] = a.y;
        sVT[(8 + fl) * 66 + n] = a.z;
        sVT[(16 + fl) * 66 + n] = a.w;
        sAgS[fl * 66 + n] = b.x;
        sAgV[fl * 66 + n] = b.y;
        sAgV[(8 + fl) * 66 + n] = b.z;
        sAgV[(16 + fl) * 66 + n] = b.w;
    }
    for (int i = tid; i < 4096; i += 256) {
        int a = i & 63, n = i >> 6;
        int gn = base + n;
        sAtT[a * 68 + n] = (gn < NN) ? attrs[(long)gn * 64 + a] : 0.0f;
    }

    ULL acc0[4] = {0,0,0,0}, acc1[4] = {0,0,0,0}, acc2[4] = {0,0,0,0},
        acc3[4] = {0,0,0,0}, acc4[4] = {0,0,0,0};

    int qi = 0;
    for (int fl = 0; fl < 8; fl++) {
        int fg = F0 + fl;
        ULL Ls02 = dup2(__ldg(&Ls[fg * 64 + tx]));
        ULL Ls12 = dup2(__ldg(&Ls[fg * 64 + 32 + tx]));
        ULL Lv02 = dup2(__ldg(&Lv[fg * 32 + tx]));

        if (fl == 0) __syncthreads();   // node arrays ready

        // lin parts
#pragma unroll
        for (int P = 0; P < 4; P++) {
            int nn = nA + 2 * P;
            ULL ag = *(const ULL*)&sAgS[fl * 66 + nn];
            fma2(acc0[P], ag, Ls02);
            fma2(acc1[P], ag, Ls12);
            fma2(acc2[P], *(const ULL*)&sAgV[fl * 66 + nn], Lv02);
            fma2(acc3[P], *(const ULL*)&sAgV[(8 + fl) * 66 + nn], Lv02);
            fma2(acc4[P], *(const ULL*)&sAgV[(16 + fl) * 66 + nn], Lv02);
        }

        // a-first accumulators
        ULL E0[4] = {0,0,0,0}, E1[4] = {0,0,0,0}, Dd[4] = {0,0,0,0};

#pragma unroll 1
        for (int q = 0; q < 4; q++, qi++) {
            if (qi + 2 < 32) node_issue_stage(sW, Wd, qi + 2, tid);
            CP_COMMIT;
            asm volatile("cp.async.wait_group 2;");
            __syncthreads();

            const float* sWq = sW + (qi & 3) * 3072;
#pragma unroll 4
            for (int aa = 0; aa < 16; aa++) {
                int ag_ = q * 16 + aa;
                ULL W02  = *(const ULL*)&sWq[aa * 192 + tx * 2];
                ULL W12  = *(const ULL*)&sWq[aa * 192 + 64 + tx * 2];
                ULL Wv02 = *(const ULL*)&sWq[aa * 192 + 128 + tx * 2];
                ulonglong2 atA = *(const ulonglong2*)&sAtT[ag_ * 68 + nA];
                ulonglong2 atB = *(const ulonglong2*)&sAtT[ag_ * 68 + nA + 4];
                fma2(E0[0], atA.x, W02); fma2(E1[0], atA.x, W12); fma2(Dd[0], atA.x, Wv02);
                fma2(E0[1], atA.y, W02); fma2(E1[1], atA.y, W12); fma2(Dd[1], atA.y, Wv02);
                fma2(E0[2], atB.x, W02); fma2(E1[2], atB.x, W12); fma2(Dd[2], atB.x, Wv02);
                fma2(E0[3], atB.y, W02); fma2(E1[3], atB.y, W12); fma2(Dd[3], atB.y, Wv02);
            }
        }

        // per-f epilogue
#pragma unroll
        for (int P = 0; P < 4; P++) {
            int nn = nA + 2 * P;
            ULL sf2 = *(const ULL*)&sST[fl * 66 + nn];
            fma2(acc0[P], sf2, E0[P]);
            fma2(acc1[P], sf2, E1[P]);
            fma2(acc2[P], *(const ULL*)&sVT[fl * 66 + nn], Dd[P]);
            fma2(acc3[P], *(const ULL*)&sVT[(8 + fl) * 66 + nn], Dd[P]);
            fma2(acc4[P], *(const ULL*)&sVT[(16 + fl) * 66 + nn], Dd[P]);
        }
    }

    // epilogue: plain coalesced stores into this f-split's private slab
    float* slab = g_pre4 + (long)fsp * NN * 160;
#pragma unroll
    for (int P = 0; P < 4; P++) {
        float ft[2], gt[2], a2[2], a3[2], a4[2];
        upk2(acc0[P], ft[0], ft[1]);
        upk2(acc1[P], gt[0], gt[1]);
        upk2(acc2[P], a2[0], a2[1]);
        upk2(acc3[P], a3[0], a3[1]);
        upk2(acc4[P], a4[0], a4[1]);
#pragma unroll
        for (int h = 0; h < 2; h++) {
            int gn = base + nA + 2 * P + h;
            if (gn < NN) {
                float* p = slab + (long)gn * 160 + tx;
                p[0]   = ft[h];
                p[32]  = gt[h];
                p[64]  = a2[h];
                p[96]  = a3[h];
                p[128] = a4[h];
            }
        }
    }
}

// ---------------- node epilogue: sum 4 slabs + activation + residual --------
__global__ void epi_kernel() {
    int idx = blockIdx.x * 256 + threadIdx.x;
    if (idx >= NN * 32) return;
    int n = idx >> 5, tx = idx & 31;
    float ft = 0.f, gt = 0.f, a2 = 0.f, a3 = 0.f, a4 = 0.f;
#pragma unroll
    for (int k = 0; k < 4; k++) {
        const float* p = g_pre4 + (long)k * NN * 160 + (long)n * 160 + tx;
        ft += p[0]; gt += p[32]; a2 += p[64]; a3 += p[96]; a4 += p[128];
    }
    float4 o = ((float4*)g_sv)[idx];
    float sg = fsig(gt);
    float s_new = fsilu(ft) + o.x;
    ((float4*)g_sv)[idx] =
        make_float4(s_new, a2 * sg + o.y, a3 * sg + o.z, a4 * sg + o.w);
}

// ---------------- output assembly -------------------------------------------
__global__ void out_kernel(float* __restrict__ out) {
    int idx = blockIdx.x * 256 + threadIdx.x;
    if (idx >= NN * 128) return;
    int n = idx >> 7, j = idx & 127;
    float val;
    if (j < 32) {
        val = g_sv[((long)n * 32 + j) * 4];
    } else {
        int t = j - 32;
        int f = t / 3;
        int c = t - 3 * f;
        val = g_sv[((long)n * 32 + f) * 4 + 1 + c];
    }
    out[idx] = val;
}

// ---------------- launch -----------------------------------------------------
extern "C" void kernel_launch(void* const* d_in, const int* in_sizes, int n_in,
                              void* d_out, int out_size) {
    const float* attrs  = (const float*)d_in[0];
    const float* coords = (const float*)d_in[1];
    const int*   eidx   = (const int*)d_in[2];
    const float* embW   = (const float*)d_in[3];
    const float* rW1    = (const float*)d_in[4];
    const float* rb1    = (const float*)d_in[5];
    const float* rW2    = (const float*)d_in[6];
    const float* Ls     = (const float*)d_in[7];
    const float* Lv     = (const float*)d_in[8];
    const float* Ws     = (const float*)d_in[9];
    const float* Wv     = (const float*)d_in[10];
    float* out = (float*)d_out;

    cudaFuncSetAttribute(node_kernel,
                         cudaFuncAttributeMaxDynamicSharedMemorySize,
                         NODE_SMEM_BYTES);

    void *pagg = nullptr, *pwd = nullptr, *ptab = nullptr, *ptabS = nullptr;
    cudaGetSymbolAddress(&pagg, g_agg);
    cudaGetSymbolAddress(&pwd, g_wdup);
    cudaGetSymbolAddress(&ptab, g_tab);
    cudaGetSymbolAddress(&ptabS, g_tabS);

    tab_kernel<<<2 * TT, 160>>>(rW1, rb1, rW2);
    slope_kernel<<<(2 * TT * 160 + 255) / 256, 256>>>();
    dupw_kernel<<<3072, 256>>>(Ws, Wv);
    geom_kernel<<<(EE + 255) / 256, 256>>>(coords, eidx);
    emb_kernel<<<NN * 32 / 256, 256>>>(attrs, embW);

    for (int l = 0; l < 2; l++) {
        cudaMemsetAsync(pagg, 0, NN * 128 * sizeof(float));
        edge_kernel<<<1184, 256>>>(
            (const float*)ptab + (long)l * TT * 160,
            (const __nv_bfloat16*)ptabS + (long)l * TT * 160);
        node_kernel<<<NTILES * 4, 256, NODE_SMEM_BYTES>>>(
            attrs, Ls + l * 2048, Lv + l * 1024,
            (const float*)pwd + (long)l * 393216);
        epi_kernel<<<(NN * 32 + 255) / 256, 256>>>();
    }
    out_kernel<<<(NN * 128 + 255) / 256, 256>>>(out);
}

// round 15
// speedup vs baseline: 1.1966x; 1.0106x over previous
#include <cuda_runtime.h>
#include <cuda_bf16.h>
#include <math.h>

#define NN 20000
#define EE 640000
#define TT 4096

typedef unsigned long long ULL;

// ---------------- packed f32x2 helpers -------------------------------------
__device__ __forceinline__ ULL pk2(float lo, float hi) {
    ULL r; asm("mov.b64 %0,{%1,%2};" : "=l"(r) : "f"(lo), "f"(hi)); return r;
}
__device__ __forceinline__ ULL dup2(float v) { return pk2(v, v); }
__device__ __forceinline__ void upk2(ULL v, float& lo, float& hi) {
    asm("mov.b64 {%0,%1},%2;" : "=f"(lo), "=f"(hi) : "l"(v));
}
__device__ __forceinline__ void fma2(ULL& d, ULL a, ULL b) {
    asm("fma.rn.f32x2 %0,%1,%2,%0;" : "+l"(d) : "l"(a), "l"(b));
}
__device__ __forceinline__ ULL mul2(ULL a, ULL b) {
    ULL d; asm("mul.rn.f32x2 %0,%1,%2;" : "=l"(d) : "l"(a), "l"(b)); return d;
}

// ---------------- cp.async helpers ------------------------------------------
__device__ __forceinline__ void cpa16(void* smem_dst, const void* gsrc) {
    unsigned s = (unsigned)__cvta_generic_to_shared(smem_dst);
    asm volatile("cp.async.cg.shared.global [%0],[%1],16;" :: "r"(s), "l"(gsrc));
}
#define CP_COMMIT asm volatile("cp.async.commit_group;")

// ---------------- vector RED ------------------------------------------------
__device__ __forceinline__ void red_v4(float* p, float a, float b, float c, float d) {
    asm volatile("red.global.add.v4.f32 [%0],{%1,%2,%3,%4};"
                 :: "l"(p), "f"(a), "f"(b), "f"(c), "f"(d) : "memory");
}

__device__ __forceinline__ float fsilu(float x) {
    return x * __fdividef(1.0f, 1.0f + __expf(-x));
}
__device__ __forceinline__ float fsig(float x) {
    return __fdividef(1.0f, 1.0f + __expf(-x));
}

// ---------------- scratch ----------------------------------------------------
__device__ float4 g_geo[EE];        // {x, Y0, Y1, Y2}
__device__ int2   g_se[EE];         // {snd, rcv}
__device__ float  g_sv[NN * 128];   // [n][f]{s,v0,v1,v2} packed float4
__device__ float  g_agg[NN * 128];  // same packing
__device__ float  g_pre[NN * 160];  // [n][p][32]
__device__ float  g_wdup[786432];   // duplicated node weights, 2 layers
__device__ float  g_tab[2 * TT * 160];             // radial values * INV
__device__ __nv_bfloat16 g_tabS[2 * TT * 160];     // slopes (bf16)

// ---------------- radial table build (runs once, 2*4096 points) -------------
__global__ void tab_kernel(const float* __restrict__ rW1,
                           const float* __restrict__ rb1,
                           const float* __restrict__ rW2) {
    int l = blockIdx.x >> 12;
    int i = blockIdx.x & (TT - 1);
    int tid = threadIdx.x;       // 160 threads
    __shared__ float H[64];
    float x = (float)i * (1.0f / (float)(TT - 1));
    float xe = fmaxf(x, 1e-7f);
    if (tid < 64) {
        float r = 5.0f * xe;
        float x3 = xe * xe * xe;
        float x6 = x3 * x3;
        float x7 = x6 * xe;
        float x8 = x7 * xe;
        float fc = (xe < 1.0f) ? (1.0f - 28.0f * x6 + 48.0f * x7 - 21.0f * x8) : 0.0f;
        float c = 0.6324555320336759f * fc / r;
        float acc = rb1[l * 64 + tid];
#pragma unroll
        for (int n = 1; n <= 8; n++) {
            float ef = c * sinf((float)n * 3.14159265358979323846f * xe);
            acc += ef * rW1[l * 512 + (n - 1) * 64 + tid];
        }
        H[tid] = acc / (1.0f + expf(-acc));
    }
    __syncthreads();
    float out = 0.0f;
#pragma unroll 8
    for (int k = 0; k < 64; k++)
        out += H[k] * rW2[l * 10240 + k * 160 + tid];
    g_tab[((long)l * TT + i) * 160 + tid] = out * 0.17677669529663689f;
}

// ---------------- slope table (bf16) -----------------------------------------
__global__ void slope_kernel() {
    int idx = blockIdx.x * 256 + threadIdx.x;
    if (idx >= 2 * TT * 160) return;
    int i = (idx / 160) & (TT - 1);
    float v = g_tab[idx];
    float vn = (i < TT - 1) ? g_tab[idx + 160] : v;
    g_tabS[idx] = __float2bfloat16(vn - v);
}

// ---------------- weight duplication (runs once) ----------------------------
__global__ void dupw_kernel(const float* __restrict__ Ws,
                            const float* __restrict__ Wv) {
    int idx = blockIdx.x * 256 + threadIdx.x;   // < 786432
    int l = idx / 393216;
    int rem = idx - l * 393216;
    int f = rem / 12288;
    int a = (rem / 192) % 64;
    int c = rem % 192;
    float v;
    if (c < 128)
        v = Ws[(long)l * 131072 + f * 4096 + a * 64 + (c >> 1)];
    else
        v = Wv[(long)l * 65536 + f * 2048 + a * 32 + ((c - 128) >> 1)];
    g_wdup[idx] = v;
}

// ---------------- edge geometry ---------------------------------------------
__global__ void geom_kernel(const float* __restrict__ coords,
                            const int* __restrict__ eidx) {
    int e = blockIdx.x * blockDim.x + threadIdx.x;
    if (e >= EE) return;
    int snd = eidx[e];
    int rcv = eidx[EE + e];
    float dx = coords[snd * 3 + 0] - coords[rcv * 3 + 0];
    float dy = coords[snd * 3 + 1] - coords[rcv * 3 + 1];
    float dz = coords[snd * 3 + 2] - coords[rcv * 3 + 2];
    float r = sqrtf(dx * dx + dy * dy + dz * dz + 1e-12f);
    float invr = 1.0f / r;
    float sc = 1.7320508075688772f * invr;
    g_geo[e] = make_float4(r * 0.2f, sc * dx, sc * dy, sc * dz);
    g_se[e] = make_int2(snd, rcv);
}

// ---------------- node embedding -------------------------------------------
__global__ void emb_kernel(const float* __restrict__ attrs,
                           const float* __restrict__ W) {
    int gid = blockIdx.x * 256 + threadIdx.x;
    int n = gid >> 5;
    int f = gid & 31;
    float acc = 0.0f;
#pragma unroll 8
    for (int a = 0; a < 64; a++) acc += attrs[n * 64 + a] * W[a * 32 + f];
    ((float4*)g_sv)[gid] = make_float4(acc, 0.0f, 0.0f, 0.0f);
}

// ---------------- edge kernel: bf16-slope table lerp + message + scatter ----
// unsorted edges, per-edge independent red.v4 (max MLP) — proven R10 version
__global__ __launch_bounds__(256) void edge_kernel(
        const float* __restrict__ tabV,
        const __nv_bfloat16* __restrict__ tabS) {
    int gw = (blockIdx.x * 256 + threadIdx.x) >> 5;
    int tx = threadIdx.x & 31;
    int nw = (gridDim.x * 256) >> 5;
    int per = (EE + nw - 1) / nw;
    int e0 = gw * per;
    int e1 = min(e0 + per, EE);

    const float4* sv4 = (const float4*)g_sv;

    for (int e = e0; e < e1; e++) {
        int2 sr = __ldg(&g_se[e]);
        float4 gy = __ldg(&g_geo[e]);

        float u = fminf(gy.x, 1.0f) * (float)(TT - 1);
        int ix = min((int)u, TT - 2);
        float fr = u - (float)ix;

        const float* vp = tabV + (long)ix * 160 + tx;
        const __nv_bfloat16* sp = tabS + (long)ix * 160 + tx;
        float w[5];
#pragma unroll
        for (int p = 0; p < 5; p++) {
            float sl = __bfloat162float(__ldg(sp + p * 32));
            w[p] = fmaf(fr, sl, __ldg(vp + p * 32));
        }

        float4 sv = __ldg(&sv4[(long)sr.x * 32 + tx]);
        float y0 = gy.y, y1 = gy.z, y2 = gy.w;
        float sj = sv.x, vj0 = sv.y, vj1 = sv.z, vj2 = sv.w;
        float dot = vj0 * y0 + vj1 * y1 + vj2 * y2;
        float cx = vj1 * y2 - vj2 * y1;
        float cy = vj2 * y0 - vj0 * y2;
        float cz = vj0 * y1 - vj1 * y0;
        float ms  = w[0] * sj + w[3] * dot;             // INV folded in table
        float mv0 = w[1] * sj * y0 + w[2] * vj0 + w[4] * cx;
        float mv1 = w[1] * sj * y1 + w[2] * vj1 + w[4] * cy;
        float mv2 = w[1] * sj * y2 + w[2] * vj2 + w[4] * cz;
        red_v4(&g_agg[((long)sr.y * 32 + tx) * 4], ms, mv0, mv1, mv2);
    }
}

// ---------------- node update (64-node tiles, f-split 4, a-first factoring) -
// PROVEN R10 version: 4-slot ring, 2 CTAs/SM
#define NODE_SMEM_BYTES (20864 * 4)
#define NTILES 313   // ceil(20000/64)

__device__ __forceinline__ void node_issue_stage(float* ring,
        const float* __restrict__ Wd, int s, int tid) {
    float* dst = ring + (s & 3) * 3072;
    const float4* src = (const float4*)(Wd + (s >> 2) * 12288 + (s & 3) * 3072);
    float4* d = (float4*)dst;
#pragma unroll
    for (int i = 0; i < 3; i++) cpa16(d + tid + i * 256, src + tid + i * 256);
}

__global__ __launch_bounds__(256, 2) void node_kernel(
    const float* __restrict__ attrs,
    const float* __restrict__ Ls, const float* __restrict__ Lv,
    const float* __restrict__ Wdup) {
    extern __shared__ float sm[];
    float* sW   = sm;            // 4 x 3072 ring
    float* sAtT = sm + 12288;    // [a][n] stride 68
    float* sST  = sAtT + 4352;   // [f_local][n] stride 66 (8 rows)
    float* sVT  = sST + 528;     // [c*8+f_local][n] stride 66 (24 rows)
    float* sAgS = sVT + 1584;
    float* sAgV = sAgS + 528;

    int tid = threadIdx.x, tx = tid & 31, ty = tid >> 5;
    int tile = blockIdx.x >> 2;
    int F0 = (blockIdx.x & 3) * 8;
    int base = tile * 64;
    int nA = ty * 8;
    const float* Wd = Wdup + (long)F0 * 12288;

    node_issue_stage(sW, Wd, 0, tid); CP_COMMIT;
    node_issue_stage(sW, Wd, 1, tid); CP_COMMIT;

    const float4* sv4 = (const float4*)g_sv;
    const float4* ag4 = (const float4*)g_agg;
    for (int i = tid; i < 512; i += 256) {
        int fl = i & 7, n = i >> 3;
        int gn = base + n;
        float4 a = (gn < NN) ? sv4[(long)gn * 32 + F0 + fl]
                             : make_float4(0.f, 0.f, 0.f, 0.f);
        float4 b = (gn < NN) ? ag4[(long)gn * 32 + F0 + fl]
                             : make_float4(0.f, 0.f, 0.f, 0.f);
        sST[fl * 66 + n] = a.x;
        sVT[fl * 66 + n] = a.y;
        sVT[(8 + fl) * 66 + n] = a.z;
        sVT[(16 + fl) * 66 + n] = a.w;
        sAgS[fl * 66 + n] = b.x;
        sAgV[fl * 66 + n] = b.y;
        sAgV[(8 + fl) * 66 + n] = b.z;
        sAgV[(16 + fl) * 66 + n] = b.w;
    }
    for (int i = tid; i < 4096; i += 256) {
        int a = i & 63, n = i >> 6;
        int gn = base + n;
        sAtT[a * 68 + n] = (gn < NN) ? attrs[(long)gn * 64 + a] : 0.0f;
    }

    ULL acc0[4] = {0,0,0,0}, acc1[4] = {0,0,0,0}, acc2[4] = {0,0,0,0},
        acc3[4] = {0,0,0,0}, acc4[4] = {0,0,0,0};

    int qi = 0;
    for (int fl = 0; fl < 8; fl++) {
        int fg = F0 + fl;
        ULL Ls02 = dup2(__ldg(&Ls[fg * 64 + tx]));
        ULL Ls12 = dup2(__ldg(&Ls[fg * 64 + 32 + tx]));
        ULL Lv02 = dup2(__ldg(&Lv[fg * 32 + tx]));

        if (fl == 0) __syncthreads();   // node arrays ready

        // lin parts
#pragma unroll
        for (int P = 0; P < 4; P++) {
            int nn = nA + 2 * P;
            ULL ag = *(const ULL*)&sAgS[fl * 66 + nn];
            fma2(acc0[P], ag, Ls02);
            fma2(acc1[P], ag, Ls12);
            fma2(acc2[P], *(const ULL*)&sAgV[fl * 66 + nn], Lv02);
            fma2(acc3[P], *(const ULL*)&sAgV[(8 + fl) * 66 + nn], Lv02);
            fma2(acc4[P], *(const ULL*)&sAgV[(16 + fl) * 66 + nn], Lv02);
        }

        // a-first accumulators
        ULL E0[4] = {0,0,0,0}, E1[4] = {0,0,0,0}, Dd[4] = {0,0,0,0};

#pragma unroll 1
        for (int q = 0; q < 4; q++, qi++) {
            if (qi + 2 < 32) node_issue_stage(sW, Wd, qi + 2, tid);
            CP_COMMIT;
            asm volatile("cp.async.wait_group 2;");
            __syncthreads();

            const float* sWq = sW + (qi & 3) * 3072;
#pragma unroll 4
            for (int aa = 0; aa < 16; aa++) {
                int ag_ = q * 16 + aa;
                ULL W02  = *(const ULL*)&sWq[aa * 192 + tx * 2];
                ULL W12  = *(const ULL*)&sWq[aa * 192 + 64 + tx * 2];
                ULL Wv02 = *(const ULL*)&sWq[aa * 192 + 128 + tx * 2];
                ulonglong2 atA = *(const ulonglong2*)&sAtT[ag_ * 68 + nA];
                ulonglong2 atB = *(const ulonglong2*)&sAtT[ag_ * 68 + nA + 4];
                fma2(E0[0], atA.x, W02); fma2(E1[0], atA.x, W12); fma2(Dd[0], atA.x, Wv02);
                fma2(E0[1], atA.y, W02); fma2(E1[1], atA.y, W12); fma2(Dd[1], atA.y, Wv02);
                fma2(E0[2], atB.x, W02); fma2(E1[2], atB.x, W12); fma2(Dd[2], atB.x, Wv02);
                fma2(E0[3], atB.y, W02); fma2(E1[3], atB.y, W12); fma2(Dd[3], atB.y, Wv02);
            }
        }

        // per-f epilogue
#pragma unroll
        for (int P = 0; P < 4; P++) {
            int nn = nA + 2 * P;
            ULL sf2 = *(const ULL*)&sST[fl * 66 + nn];
            fma2(acc0[P], sf2, E0[P]);
            fma2(acc1[P], sf2, E1[P]);
            fma2(acc2[P], *(const ULL*)&sVT[fl * 66 + nn], Dd[P]);
            fma2(acc3[P], *(const ULL*)&sVT[(8 + fl) * 66 + nn], Dd[P]);
            fma2(acc4[P], *(const ULL*)&sVT[(16 + fl) * 66 + nn], Dd[P]);
        }
    }

    // epilogue: RED partial sums into g_pre
#pragma unroll
    for (int P = 0; P < 4; P++) {
        float ft[2], gt[2], a2[2], a3[2], a4[2];
        upk2(acc0[P], ft[0], ft[1]);
        upk2(acc1[P], gt[0], gt[1]);
        upk2(acc2[P], a2[0], a2[1]);
        upk2(acc3[P], a3[0], a3[1]);
        upk2(acc4[P], a4[0], a4[1]);
#pragma unroll
        for (int h = 0; h < 2; h++) {
            int gn = base + nA + 2 * P + h;
            if (gn < NN) {
                float* p = g_pre + (long)gn * 160 + tx;
                atomicAdd(p, ft[h]);
                atomicAdd(p + 32, gt[h]);
                atomicAdd(p + 64, a2[h]);
                atomicAdd(p + 96, a3[h]);
                atomicAdd(p + 128, a4[h]);
            }
        }
    }
}

// ---------------- node epilogue: activation + residual + zero for next layer
__global__ void epi_kernel() {
    int idx = blockIdx.x * 256 + threadIdx.x;
    if (idx >= NN * 32) return;
    int n = idx >> 5, tx = idx & 31;
    float* p = g_pre + (long)n * 160 + tx;
    float ft = p[0], gt = p[32], a2 = p[64], a3 = p[96], a4 = p[128];
    // zero partials + agg for the next layer (replaces per-layer memsets)
    p[0] = 0.f; p[32] = 0.f; p[64] = 0.f; p[96] = 0.f; p[128] = 0.f;
    ((float4*)g_agg)[idx] = make_float4(0.f, 0.f, 0.f, 0.f);
    float4 o = ((float4*)g_sv)[idx];
    float sg = fsig(gt);
    float s_new = fsilu(ft) + o.x;
    ((float4*)g_sv)[idx] =
        make_float4(s_new, a2 * sg + o.y, a3 * sg + o.z, a4 * sg + o.w);
}

// ---------------- output assembly -------------------------------------------
__global__ void out_kernel(float* __restrict__ out) {
    int idx = blockIdx.x * 256 + threadIdx.x;
    if (idx >= NN * 128) return;
    int n = idx >> 7, j = idx & 127;
    float val;
    if (j < 32) {
        val = g_sv[((long)n * 32 + j) * 4];
    } else {
        int t = j - 32;
        int f = t / 3;
        int c = t - 3 * f;
        val = g_sv[((long)n * 32 + f) * 4 + 1 + c];
    }
    out[idx] = val;
}

// ---------------- launch -----------------------------------------------------
extern "C" void kernel_launch(void* const* d_in, const int* in_sizes, int n_in,
                              void* d_out, int out_size) {
    const float* attrs  = (const float*)d_in[0];
    const float* coords = (const float*)d_in[1];
    const int*   eidx   = (const int*)d_in[2];
    const float* embW   = (const float*)d_in[3];
    const float* rW1    = (const float*)d_in[4];
    const float* rb1    = (const float*)d_in[5];
    const float* rW2    = (const float*)d_in[6];
    const float* Ls     = (const float*)d_in[7];
    const float* Lv     = (const float*)d_in[8];
    const float* Ws     = (const float*)d_in[9];
    const float* Wv     = (const float*)d_in[10];
    float* out = (float*)d_out;

    cudaFuncSetAttribute(node_kernel,
                         cudaFuncAttributeMaxDynamicSharedMemorySize,
                         NODE_SMEM_BYTES);

    void *pagg = nullptr, *ppre = nullptr, *pwd = nullptr;
    void *ptab = nullptr, *ptabS = nullptr;
    cudaGetSymbolAddress(&pagg, g_agg);
    cudaGetSymbolAddress(&ppre, g_pre);
    cudaGetSymbolAddress(&pwd, g_wdup);
    cudaGetSymbolAddress(&ptab, g_tab);
    cudaGetSymbolAddress(&ptabS, g_tabS);

    // one-time zeroing for layer 0 (epi re-zeros for the next layer/replay;
    // these memsets run every replay at graph start, overlapping prep kernels)
    cudaMemsetAsync(pagg, 0, NN * 128 * sizeof(float));
    cudaMemsetAsync(ppre, 0, NN * 160 * sizeof(float));
    tab_kernel<<<2 * TT, 160>>>(rW1, rb1, rW2);
    slope_kernel<<<(2 * TT * 160 + 255) / 256, 256>>>();
    dupw_kernel<<<3072, 256>>>(Ws, Wv);
    geom_kernel<<<(EE + 255) / 256, 256>>>(coords, eidx);
    emb_kernel<<<NN * 32 / 256, 256>>>(attrs, embW);

    for (int l = 0; l < 2; l++) {
        edge_kernel<<<1184, 256>>>(
            (const float*)ptab + (long)l * TT * 160,
            (const __nv_bfloat16*)ptabS + (long)l * TT * 160);
        node_kernel<<<NTILES * 4, 256, NODE_SMEM_BYTES>>>(
            attrs, Ls + l * 2048, Lv + l * 1024,
            (const float*)pwd + (long)l * 393216);
        epi_kernel<<<(NN * 32 + 255) / 256, 256>>>();
    }
    out_kernel<<<(NN * 128 + 255) / 256, 256>>>(out);
}

// round 16
// speedup vs baseline: 1.2481x; 1.0431x over previous
#include <cuda_runtime.h>
#include <cuda_bf16.h>
#include <math.h>

#define NN 20000
#define EE 640000
#define TT 4096

typedef unsigned long long ULL;

// ---------------- packed f32x2 helpers -------------------------------------
__device__ __forceinline__ ULL pk2(float lo, float hi) {
    ULL r; asm("mov.b64 %0,{%1,%2};" : "=l"(r) : "f"(lo), "f"(hi)); return r;
}
__device__ __forceinline__ ULL dup2(float v) { return pk2(v, v); }
__device__ __forceinline__ void upk2(ULL v, float& lo, float& hi) {
    asm("mov.b64 {%0,%1},%2;" : "=f"(lo), "=f"(hi) : "l"(v));
}
__device__ __forceinline__ void fma2(ULL& d, ULL a, ULL b) {
    asm("fma.rn.f32x2 %0,%1,%2,%0;" : "+l"(d) : "l"(a), "l"(b));
}
__device__ __forceinline__ ULL mul2(ULL a, ULL b) {
    ULL d; asm("mul.rn.f32x2 %0,%1,%2;" : "=l"(d) : "l"(a), "l"(b)); return d;
}

// ---------------- cp.async helpers ------------------------------------------
__device__ __forceinline__ void cpa16(void* smem_dst, const void* gsrc) {
    unsigned s = (unsigned)__cvta_generic_to_shared(smem_dst);
    asm volatile("cp.async.cg.shared.global [%0],[%1],16;" :: "r"(s), "l"(gsrc));
}
#define CP_COMMIT asm volatile("cp.async.commit_group;")

// ---------------- vector RED ------------------------------------------------
__device__ __forceinline__ void red_v4(float* p, float a, float b, float c, float d) {
    asm volatile("red.global.add.v4.f32 [%0],{%1,%2,%3,%4};"
                 :: "l"(p), "f"(a), "f"(b), "f"(c), "f"(d) : "memory");
}

__device__ __forceinline__ float fsilu(float x) {
    return x * __fdividef(1.0f, 1.0f + __expf(-x));
}
__device__ __forceinline__ float fsig(float x) {
    return __fdividef(1.0f, 1.0f + __expf(-x));
}

// ---------------- scratch ----------------------------------------------------
__device__ float4 g_geo[EE];        // {x, Y0, Y1, Y2}
__device__ int2   g_se[EE];         // {snd, rcv}
__device__ float  g_sv[NN * 128];   // [n][f]{s,v0,v1,v2} packed float4
__device__ float  g_agg[NN * 128];  // same packing
__device__ float  g_pre[NN * 160];  // [n][p][32]
__device__ float  g_wdup[786432];   // duplicated node weights, 2 layers
__device__ float  g_tab[2 * TT * 160];             // radial values * INV
__device__ __nv_bfloat16 g_tabS[2 * TT * 160];     // slopes (bf16)

// ---------------- radial table build (runs once, 2*4096 points) -------------
__global__ void tab_kernel(const float* __restrict__ rW1,
                           const float* __restrict__ rb1,
                           const float* __restrict__ rW2) {
    int l = blockIdx.x >> 12;
    int i = blockIdx.x & (TT - 1);
    int tid = threadIdx.x;       // 160 threads
    __shared__ float H[64];
    float x = (float)i * (1.0f / (float)(TT - 1));
    float xe = fmaxf(x, 1e-7f);
    if (tid < 64) {
        float r = 5.0f * xe;
        float x3 = xe * xe * xe;
        float x6 = x3 * x3;
        float x7 = x6 * xe;
        float x8 = x7 * xe;
        float fc = (xe < 1.0f) ? (1.0f - 28.0f * x6 + 48.0f * x7 - 21.0f * x8) : 0.0f;
        float c = 0.6324555320336759f * fc / r;
        float acc = rb1[l * 64 + tid];
#pragma unroll
        for (int n = 1; n <= 8; n++) {
            float ef = c * sinf((float)n * 3.14159265358979323846f * xe);
            acc += ef * rW1[l * 512 + (n - 1) * 64 + tid];
        }
        H[tid] = acc / (1.0f + expf(-acc));
    }
    __syncthreads();
    float out = 0.0f;
#pragma unroll 8
    for (int k = 0; k < 64; k++)
        out += H[k] * rW2[l * 10240 + k * 160 + tid];
    g_tab[((long)l * TT + i) * 160 + tid] = out * 0.17677669529663689f;
}

// ---------------- slope table (bf16) -----------------------------------------
__global__ void slope_kernel() {
    int idx = blockIdx.x * 256 + threadIdx.x;
    if (idx >= 2 * TT * 160) return;
    int i = (idx / 160) & (TT - 1);
    float v = g_tab[idx];
    float vn = (i < TT - 1) ? g_tab[idx + 160] : v;
    g_tabS[idx] = __float2bfloat16(vn - v);
}

// ---------------- weight duplication (runs once) ----------------------------
// New interleaved layout per (l, f, a) block of 192 floats:
//   c in [0,128): groups of 4 per lane tx=c>>2: {Ws0,Ws0,Ws1,Ws1}
//                 Ws0 = Ws[f][a][tx], Ws1 = Ws[f][a][32+tx]
//   c in [128,192): Wv dup pairs: Wv[f][a][(c-128)>>1]
__global__ void dupw_kernel(const float* __restrict__ Ws,
                            const float* __restrict__ Wv) {
    int idx = blockIdx.x * 256 + threadIdx.x;   // < 786432
    int l = idx / 393216;
    int rem = idx - l * 393216;
    int f = rem / 12288;
    int a = (rem / 192) % 64;
    int c = rem % 192;
    float v;
    if (c < 128) {
        int g = (c >> 2) + ((c & 2) ? 32 : 0);
        v = Ws[(long)l * 131072 + f * 4096 + a * 64 + g];
    } else {
        v = Wv[(long)l * 65536 + f * 2048 + a * 32 + ((c - 128) >> 1)];
    }
    g_wdup[idx] = v;
}

// ---------------- edge geometry ---------------------------------------------
__global__ void geom_kernel(const float* __restrict__ coords,
                            const int* __restrict__ eidx) {
    int e = blockIdx.x * blockDim.x + threadIdx.x;
    if (e >= EE) return;
    int snd = eidx[e];
    int rcv = eidx[EE + e];
    float dx = coords[snd * 3 + 0] - coords[rcv * 3 + 0];
    float dy = coords[snd * 3 + 1] - coords[rcv * 3 + 1];
    float dz = coords[snd * 3 + 2] - coords[rcv * 3 + 2];
    float r = sqrtf(dx * dx + dy * dy + dz * dz + 1e-12f);
    float invr = 1.0f / r;
    float sc = 1.7320508075688772f * invr;
    g_geo[e] = make_float4(r * 0.2f, sc * dx, sc * dy, sc * dz);
    g_se[e] = make_int2(snd, rcv);
}

// ---------------- node embedding (float4 attr rows, 4x MLP) -----------------
__global__ void emb_kernel(const float* __restrict__ attrs,
                           const float* __restrict__ W) {
    int gid = blockIdx.x * 256 + threadIdx.x;
    int n = gid >> 5;
    int f = gid & 31;
    const float4* ar = (const float4*)(attrs + (long)n * 64);
    float acc = 0.0f;
#pragma unroll
    for (int a4 = 0; a4 < 16; a4++) {
        float4 av = __ldg(&ar[a4]);
        acc += av.x * W[(a4 * 4 + 0) * 32 + f];
        acc += av.y * W[(a4 * 4 + 1) * 32 + f];
        acc += av.z * W[(a4 * 4 + 2) * 32 + f];
        acc += av.w * W[(a4 * 4 + 3) * 32 + f];
    }
    ((float4*)g_sv)[gid] = make_float4(acc, 0.0f, 0.0f, 0.0f);
}

// ---------------- edge kernel: bf16-slope table lerp + message + scatter ----
// unsorted edges, per-edge independent red.v4 (max MLP) — proven R10 version
__global__ __launch_bounds__(256) void edge_kernel(
        const float* __restrict__ tabV,
        const __nv_bfloat16* __restrict__ tabS) {
    int gw = (blockIdx.x * 256 + threadIdx.x) >> 5;
    int tx = threadIdx.x & 31;
    int nw = (gridDim.x * 256) >> 5;
    int per = (EE + nw - 1) / nw;
    int e0 = gw * per;
    int e1 = min(e0 + per, EE);

    const float4* sv4 = (const float4*)g_sv;

    for (int e = e0; e < e1; e++) {
        int2 sr = __ldg(&g_se[e]);
        float4 gy = __ldg(&g_geo[e]);

        float u = fminf(gy.x, 1.0f) * (float)(TT - 1);
        int ix = min((int)u, TT - 2);
        float fr = u - (float)ix;

        const float* vp = tabV + (long)ix * 160 + tx;
        const __nv_bfloat16* sp = tabS + (long)ix * 160 + tx;
        float w[5];
#pragma unroll
        for (int p = 0; p < 5; p++) {
            float sl = __bfloat162float(__ldg(sp + p * 32));
            w[p] = fmaf(fr, sl, __ldg(vp + p * 32));
        }

        float4 sv = __ldg(&sv4[(long)sr.x * 32 + tx]);
        float y0 = gy.y, y1 = gy.z, y2 = gy.w;
        float sj = sv.x, vj0 = sv.y, vj1 = sv.z, vj2 = sv.w;
        float dot = vj0 * y0 + vj1 * y1 + vj2 * y2;
        float cx = vj1 * y2 - vj2 * y1;
        float cy = vj2 * y0 - vj0 * y2;
        float cz = vj0 * y1 - vj1 * y0;
        float ms  = w[0] * sj + w[3] * dot;             // INV folded in table
        float mv0 = w[1] * sj * y0 + w[2] * vj0 + w[4] * cx;
        float mv1 = w[1] * sj * y1 + w[2] * vj1 + w[4] * cy;
        float mv2 = w[1] * sj * y2 + w[2] * vj2 + w[4] * cz;
        red_v4(&g_agg[((long)sr.y * 32 + tx) * 4], ms, mv0, mv1, mv2);
    }
}

// ---------------- node update (64-node tiles, f-split 4, a-first factoring) -
// PROVEN R10 structure: 4-slot ring, 2 CTAs/SM; W pair-load via LDS.128
#define NODE_SMEM_BYTES (20864 * 4)
#define NTILES 313   // ceil(20000/64)

__device__ __forceinline__ void node_issue_stage(float* ring,
        const float* __restrict__ Wd, int s, int tid) {
    float* dst = ring + (s & 3) * 3072;
    const float4* src = (const float4*)(Wd + (s >> 2) * 12288 + (s & 3) * 3072);
    float4* d = (float4*)dst;
#pragma unroll
    for (int i = 0; i < 3; i++) cpa16(d + tid + i * 256, src + tid + i * 256);
}

__global__ __launch_bounds__(256, 2) void node_kernel(
    const float* __restrict__ attrs,
    const float* __restrict__ Ls, const float* __restrict__ Lv,
    const float* __restrict__ Wdup) {
    extern __shared__ float sm[];
    float* sW   = sm;            // 4 x 3072 ring
    float* sAtT = sm + 12288;    // [a][n] stride 68
    float* sST  = sAtT + 4352;   // [f_local][n] stride 66 (8 rows)
    float* sVT  = sST + 528;     // [c*8+f_local][n] stride 66 (24 rows)
    float* sAgS = sVT + 1584;
    float* sAgV = sAgS + 528;

    int tid = threadIdx.x, tx = tid & 31, ty = tid >> 5;
    int tile = blockIdx.x >> 2;
    int F0 = (blockIdx.x & 3) * 8;
    int base = tile * 64;
    int nA = ty * 8;
    const float* Wd = Wdup + (long)F0 * 12288;

    node_issue_stage(sW, Wd, 0, tid); CP_COMMIT;
    node_issue_stage(sW, Wd, 1, tid); CP_COMMIT;

    const float4* sv4 = (const float4*)g_sv;
    const float4* ag4 = (const float4*)g_agg;
    for (int i = tid; i < 512; i += 256) {
        int fl = i & 7, n = i >> 3;
        int gn = base + n;
        float4 a = (gn < NN) ? sv4[(long)gn * 32 + F0 + fl]
                             : make_float4(0.f, 0.f, 0.f, 0.f);
        float4 b = (gn < NN) ? ag4[(long)gn * 32 + F0 + fl]
                             : make_float4(0.f, 0.f, 0.f, 0.f);
        sST[fl * 66 + n] = a.x;
        sVT[fl * 66 + n] = a.y;
        sVT[(8 + fl) * 66 + n] = a.z;
        sVT[(16 + fl) * 66 + n] = a.w;
        sAgS[fl * 66 + n] = b.x;
        sAgV[fl * 66 + n] = b.y;
        sAgV[(8 + fl) * 66 + n] = b.z;
        sAgV[(16 + fl) * 66 + n] = b.w;
    }
    for (int i = tid; i < 4096; i += 256) {
        int a = i & 63, n = i >> 6;
        int gn = base + n;
        sAtT[a * 68 + n] = (gn < NN) ? attrs[(long)gn * 64 + a] : 0.0f;
    }

    ULL acc0[4] = {0,0,0,0}, acc1[4] = {0,0,0,0}, acc2[4] = {0,0,0,0},
        acc3[4] = {0,0,0,0}, acc4[4] = {0,0,0,0};

    int qi = 0;
    for (int fl = 0; fl < 8; fl++) {
        int fg = F0 + fl;
        ULL Ls02 = dup2(__ldg(&Ls[fg * 64 + tx]));
        ULL Ls12 = dup2(__ldg(&Ls[fg * 64 + 32 + tx]));
        ULL Lv02 = dup2(__ldg(&Lv[fg * 32 + tx]));

        if (fl == 0) __syncthreads();   // node arrays ready

        // lin parts
#pragma unroll
        for (int P = 0; P < 4; P++) {
            int nn = nA + 2 * P;
            ULL ag = *(const ULL*)&sAgS[fl * 66 + nn];
            fma2(acc0[P], ag, Ls02);
            fma2(acc1[P], ag, Ls12);
            fma2(acc2[P], *(const ULL*)&sAgV[fl * 66 + nn], Lv02);
            fma2(acc3[P], *(const ULL*)&sAgV[(8 + fl) * 66 + nn], Lv02);
            fma2(acc4[P], *(const ULL*)&sAgV[(16 + fl) * 66 + nn], Lv02);
        }

        // a-first accumulators
        ULL E0[4] = {0,0,0,0}, E1[4] = {0,0,0,0}, Dd[4] = {0,0,0,0};

#pragma unroll 1
        for (int q = 0; q < 4; q++, qi++) {
            if (qi + 2 < 32) node_issue_stage(sW, Wd, qi + 2, tid);
            CP_COMMIT;
            asm volatile("cp.async.wait_group 2;");
            __syncthreads();

            const float* sWq = sW + (qi & 3) * 3072;
#pragma unroll 4
            for (int aa = 0; aa < 16; aa++) {
                int ag_ = q * 16 + aa;
                ulonglong2 Wp = *(const ulonglong2*)&sWq[aa * 192 + tx * 4];
                ULL W02 = Wp.x, W12 = Wp.y;
                ULL Wv02 = *(const ULL*)&sWq[aa * 192 + 128 + tx * 2];
                ulonglong2 atA = *(const ulonglong2*)&sAtT[ag_ * 68 + nA];
                ulonglong2 atB = *(const ulonglong2*)&sAtT[ag_ * 68 + nA + 4];
                fma2(E0[0], atA.x, W02); fma2(E1[0], atA.x, W12); fma2(Dd[0], atA.x, Wv02);
                fma2(E0[1], atA.y, W02); fma2(E1[1], atA.y, W12); fma2(Dd[1], atA.y, Wv02);
                fma2(E0[2], atB.x, W02); fma2(E1[2], atB.x, W12); fma2(Dd[2], atB.x, Wv02);
                fma2(E0[3], atB.y, W02); fma2(E1[3], atB.y, W12); fma2(Dd[3], atB.y, Wv02);
            }
        }

        // per-f epilogue
#pragma unroll
        for (int P = 0; P < 4; P++) {
            int nn = nA + 2 * P;
            ULL sf2 = *(const ULL*)&sST[fl * 66 + nn];
            fma2(acc0[P], sf2, E0[P]);
            fma2(acc1[P], sf2, E1[P]);
            fma2(acc2[P], *(const ULL*)&sVT[fl * 66 + nn], Dd[P]);
            fma2(acc3[P], *(const ULL*)&sVT[(8 + fl) * 66 + nn], Dd[P]);
            fma2(acc4[P], *(const ULL*)&sVT[(16 + fl) * 66 + nn], Dd[P]);
        }
    }

    // epilogue: RED partial sums into g_pre
#pragma unroll
    for (int P = 0; P < 4; P++) {
        float ft[2], gt[2], a2[2], a3[2], a4[2];
        upk2(acc0[P], ft[0], ft[1]);
        upk2(acc1[P], gt[0], gt[1]);
        upk2(acc2[P], a2[0], a2[1]);
        upk2(acc3[P], a3[0], a3[1]);
        upk2(acc4[P], a4[0], a4[1]);
#pragma unroll
        for (int h = 0; h < 2; h++) {
            int gn = base + nA + 2 * P + h;
            if (gn < NN) {
                float* p = g_pre + (long)gn * 160 + tx;
                atomicAdd(p, ft[h]);
                atomicAdd(p + 32, gt[h]);
                atomicAdd(p + 64, a2[h]);
                atomicAdd(p + 96, a3[h]);
                atomicAdd(p + 128, a4[h]);
            }
        }
    }
}

// ---------------- node epilogue ---------------------------------------------
__global__ void epi_kernel() {
    int idx = blockIdx.x * 256 + threadIdx.x;
    if (idx >= NN * 32) return;
    int n = idx >> 5, tx = idx & 31;
    const float* p = g_pre + (long)n * 160 + tx;
    float ft = p[0], gt = p[32], a2 = p[64], a3 = p[96], a4 = p[128];
    float4 o = ((float4*)g_sv)[idx];
    float sg = fsig(gt);
    float s_new = fsilu(ft) + o.x;
    ((float4*)g_sv)[idx] =
        make_float4(s_new, a2 * sg + o.y, a3 * sg + o.z, a4 * sg + o.w);
}

// ---------------- output assembly -------------------------------------------
__global__ void out_kernel(float* __restrict__ out) {
    int idx = blockIdx.x * 256 + threadIdx.x;
    if (idx >= NN * 128) return;
    int n = idx >> 7, j = idx & 127;
    float val;
    if (j < 32) {
        val = g_sv[((long)n * 32 + j) * 4];
    } else {
        int t = j - 32;
        int f = t / 3;
        int c = t - 3 * f;
        val = g_sv[((long)n * 32 + f) * 4 + 1 + c];
    }
    out[idx] = val;
}

// ---------------- launch -----------------------------------------------------
extern "C" void kernel_launch(void* const* d_in, const int* in_sizes, int n_in,
                              void* d_out, int out_size) {
    const float* attrs  = (const float*)d_in[0];
    const float* coords = (const float*)d_in[1];
    const int*   eidx   = (const int*)d_in[2];
    const float* embW   = (const float*)d_in[3];
    const float* rW1    = (const float*)d_in[4];
    const float* rb1    = (const float*)d_in[5];
    const float* rW2    = (const float*)d_in[6];
    const float* Ls     = (const float*)d_in[7];
    const float* Lv     = (const float*)d_in[8];
    const float* Ws     = (const float*)d_in[9];
    const float* Wv     = (const float*)d_in[10];
    float* out = (float*)d_out;

    cudaFuncSetAttribute(node_kernel,
                         cudaFuncAttributeMaxDynamicSharedMemorySize,
                         NODE_SMEM_BYTES);

    void *pagg = nullptr, *ppre = nullptr, *pwd = nullptr;
    void *ptab = nullptr, *ptabS = nullptr;
    cudaGetSymbolAddress(&pagg, g_agg);
    cudaGetSymbolAddress(&ppre, g_pre);
    cudaGetSymbolAddress(&pwd, g_wdup);
    cudaGetSymbolAddress(&ptab, g_tab);
    cudaGetSymbolAddress(&ptabS, g_tabS);

    tab_kernel<<<2 * TT, 160>>>(rW1, rb1, rW2);
    slope_kernel<<<(2 * TT * 160 + 255) / 256, 256>>>();
    dupw_kernel<<<3072, 256>>>(Ws, Wv);
    geom_kernel<<<(EE + 255) / 256, 256>>>(coords, eidx);
    emb_kernel<<<NN * 32 / 256, 256>>>(attrs, embW);

    for (int l = 0; l < 2; l++) {
        cudaMemsetAsync(pagg, 0, NN * 128 * sizeof(float));
        cudaMemsetAsync(ppre, 0, NN * 160 * sizeof(float));
        edge_kernel<<<1184, 256>>>(
            (const float*)ptab + (long)l * TT * 160,
            (const __nv_bfloat16*)ptabS + (long)l * TT * 160);
        node_kernel<<<NTILES * 4, 256, NODE_SMEM_BYTES>>>(
            attrs, Ls + l * 2048, Lv + l * 1024,
            (const float*)pwd + (long)l * 393216);
        epi_kernel<<<(NN * 32 + 255) / 256, 256>>>();
    }
    out_kernel<<<(NN * 128 + 255) / 256, 256>>>(out);
}